// round 1
// baseline (speedup 1.0000x reference)
#include <cuda_runtime.h>

#define MODEL_DIM 768
#define NHEAD 12
#define HD 64
#define BB 2
#define SEQ 2048
#define NROWS (BB * SEQ)                 // 4096
#define OUT_ELEMS ((size_t)NROWS * MODEL_DIM)                 // 3,145,728
#define ATTN_ELEMS ((size_t)BB * NHEAD * SEQ * SEQ)           // 100,663,296

// ---- device scratch (allocation-free) ----
__device__ float g_Q[BB * NHEAD * SEQ * HD];   // [B,H,S,Dh]
__device__ float g_K[BB * NHEAD * SEQ * HD];
__device__ float g_V[BB * NHEAD * SEQ * HD];
__device__ float g_ctx[NROWS * MODEL_DIM];     // [B,S,D]

// ============================================================================
// GEMM: out = X @ W^T + bias.  X:[NROWS,768] row-major, W:[768,768] row-major.
// 128x128 tile, BK=8, 256 threads, 8x8 per-thread microtile.
// split=1: write to [B,H,S,Dh] layout; split=0: plain [n,768].
// ============================================================================
__global__ __launch_bounds__(256)
void proj_kernel(const float* __restrict__ X, const float* __restrict__ W,
                 const float* __restrict__ bias, float* __restrict__ out, int split)
{
    __shared__ float Xs[8][128];
    __shared__ float Ws[8][128];
    const int tid = threadIdx.x;
    const int tx = tid & 15, ty = tid >> 4;
    const int n0 = blockIdx.y * 128;
    const int j0 = blockIdx.x * 128;
    const int lrow = tid >> 1;         // 0..127
    const int ld4  = (tid & 1) * 4;    // 0 or 4

    float acc[8][8];
#pragma unroll
    for (int i = 0; i < 8; i++)
#pragma unroll
        for (int j = 0; j < 8; j++) acc[i][j] = 0.f;

    const float* Xp = X + (size_t)(n0 + lrow) * MODEL_DIM + ld4;
    const float* Wp = W + (size_t)(j0 + lrow) * MODEL_DIM + ld4;

    for (int d0 = 0; d0 < MODEL_DIM; d0 += 8) {
        float4 xa = *(const float4*)(Xp + d0);
        float4 wa = *(const float4*)(Wp + d0);
        __syncthreads();
        Xs[ld4 + 0][lrow] = xa.x; Xs[ld4 + 1][lrow] = xa.y;
        Xs[ld4 + 2][lrow] = xa.z; Xs[ld4 + 3][lrow] = xa.w;
        Ws[ld4 + 0][lrow] = wa.x; Ws[ld4 + 1][lrow] = wa.y;
        Ws[ld4 + 2][lrow] = wa.z; Ws[ld4 + 3][lrow] = wa.w;
        __syncthreads();
#pragma unroll
        for (int kk = 0; kk < 8; kk++) {
            float a[8], b[8];
            *(float4*)&a[0] = *(const float4*)&Xs[kk][ty * 8];
            *(float4*)&a[4] = *(const float4*)&Xs[kk][ty * 8 + 4];
            *(float4*)&b[0] = *(const float4*)&Ws[kk][tx * 8];
            *(float4*)&b[4] = *(const float4*)&Ws[kk][tx * 8 + 4];
#pragma unroll
            for (int i = 0; i < 8; i++)
#pragma unroll
                for (int j = 0; j < 8; j++) acc[i][j] += a[i] * b[j];
        }
    }

#pragma unroll
    for (int i = 0; i < 8; i++) {
        int n = n0 + ty * 8 + i;
        int b = n >> 11, s = n & (SEQ - 1);
#pragma unroll
        for (int j4 = 0; j4 < 8; j4 += 4) {
            int j = j0 + tx * 8 + j4;
            float4 v;
            v.x = acc[i][j4 + 0] + bias[j + 0];
            v.y = acc[i][j4 + 1] + bias[j + 1];
            v.z = acc[i][j4 + 2] + bias[j + 2];
            v.w = acc[i][j4 + 3] + bias[j + 3];
            if (split) {
                int h = j >> 6, dh = j & 63;
                *(float4*)&out[(((size_t)(b * NHEAD + h) * SEQ + s) << 6) + dh] = v;
            } else {
                *(float4*)&out[(size_t)n * MODEL_DIM + j] = v;
            }
        }
    }
}

// ============================================================================
// Attention: per block = one (b*h, 16-q-row) tile.
// Full 16x2048 score rows live in smem -> exact single-pass softmax.
// Writes attn_weights to gmem and context into g_ctx ([B,S,D] layout).
// smem: sc[16][2048] + qs[16][64] + kvt[64*68]  = 152,576 B dynamic.
// ============================================================================
#define QT 16
#define KT 64
#define ATT_THREADS 512
#define KV_STRIDE 68
#define ATT_SMEM_FLOATS (QT * SEQ + QT * HD + KT * KV_STRIDE)
#define ATT_SMEM_BYTES (ATT_SMEM_FLOATS * 4)

__global__ __launch_bounds__(ATT_THREADS, 1)
void attn_kernel(const float* __restrict__ Qg, const float* __restrict__ Kg,
                 const float* __restrict__ Vg, float* __restrict__ attn_out,
                 float* __restrict__ ctx)
{
    extern __shared__ float sm[];
    float* sc  = sm;                       // [QT][SEQ]
    float* qs  = sm + QT * SEQ;            // [QT][HD]
    float* kvt = qs + QT * HD;             // [KT][KV_STRIDE] (transposed for K)

    const int tid = threadIdx.x;
    const int bh = blockIdx.x;             // 0..23
    const int q0 = blockIdx.y * QT;
    const size_t headbase = (size_t)bh * SEQ * HD;

    // load Q tile (contiguous)
    for (int l = tid; l < QT * HD; l += ATT_THREADS)
        qs[l] = Qg[headbase + (size_t)q0 * HD + l];

    const int i = tid >> 5;                // warp id = q-row, 0..15
    const int lane = tid & 31;
    const float scale = 0.125f;            // 1/sqrt(64)

    // ---- Phase 1: scores = Q K^T * scale ----
    for (int kt = 0; kt < SEQ; kt += KT) {
        __syncthreads();                   // kvt free (also orders qs on iter 0)
#pragma unroll
        for (int t = 0; t < 8; t++) {
            int l = tid + t * ATT_THREADS;
            int k = l >> 6, d = l & 63;
            kvt[d * KV_STRIDE + k] = Kg[headbase + (size_t)(kt + k) * HD + d];
        }
        __syncthreads();
        const int k0 = lane * 2;
        float a0 = 0.f, a1 = 0.f;
#pragma unroll
        for (int d = 0; d < HD; d++) {
            float qv = qs[i * HD + d];
            float2 kv = *(const float2*)&kvt[d * KV_STRIDE + k0];
            a0 += qv * kv.x;
            a1 += qv * kv.y;
        }
        *(float2*)&sc[i * SEQ + kt + k0] = make_float2(a0 * scale, a1 * scale);
    }
    __syncthreads();

    // ---- Phase 2: softmax (warp i owns row i) + attn write ----
    {
        float* row = sc + i * SEQ;
        float m = -1e30f;
        for (int c = lane; c < SEQ; c += 32) m = fmaxf(m, row[c]);
#pragma unroll
        for (int o = 16; o; o >>= 1) m = fmaxf(m, __shfl_xor_sync(0xFFFFFFFFu, m, o));
        float sum = 0.f;
        for (int c = lane; c < SEQ; c += 32) {
            float e = __expf(row[c] - m);
            row[c] = e;
            sum += e;
        }
#pragma unroll
        for (int o = 16; o; o >>= 1) sum += __shfl_xor_sync(0xFFFFFFFFu, sum, o);
        float inv = 1.f / sum;
        float* arow = attn_out ? attn_out + ((size_t)bh * SEQ + q0 + i) * SEQ : 0;
        for (int c = lane; c < SEQ; c += 32) {
            float p = row[c] * inv;
            row[c] = p;
            if (arow) arow[c] = p;
        }
    }
    __syncthreads();

    // ---- Phase 3: context = P @ V ----
    const int d0 = lane * 2;
    float c0 = 0.f, c1 = 0.f;
    for (int kt = 0; kt < SEQ; kt += KT) {
        __syncthreads();
#pragma unroll
        for (int t = 0; t < 8; t++) {
            int l = tid + t * ATT_THREADS;
            int k = l >> 6, d = l & 63;
            kvt[k * KV_STRIDE + d] = Vg[headbase + (size_t)(kt + k) * HD + d];
        }
        __syncthreads();
#pragma unroll 16
        for (int k = 0; k < KT; k++) {
            float p = sc[i * SEQ + kt + k];
            float2 vv = *(const float2*)&kvt[k * KV_STRIDE + d0];
            c0 += p * vv.x;
            c1 += p * vv.y;
        }
    }
    {
        int b = bh / NHEAD, h = bh % NHEAD;
        size_t o = ((size_t)(b * SEQ + q0 + i)) * MODEL_DIM + h * HD + d0;
        *(float2*)&ctx[o] = make_float2(c0, c1);
    }
}

// ============================================================================
// launch
// ============================================================================
extern "C" void kernel_launch(void* const* d_in, const int* in_sizes, int n_in,
                              void* d_out, int out_size)
{
    const float* q    = (const float*)d_in[0];
    const float* k    = (const float*)d_in[1];
    const float* v    = (const float*)d_in[2];
    const float* wq_w = (const float*)d_in[3];
    const float* wq_b = (const float*)d_in[4];
    const float* wk_w = (const float*)d_in[5];
    const float* wk_b = (const float*)d_in[6];
    const float* wv_w = (const float*)d_in[7];
    const float* wv_b = (const float*)d_in[8];
    const float* wo_w = (const float*)d_in[9];
    const float* wo_b = (const float*)d_in[10];

    float* out = (float*)d_out;
    float* attn = 0;
    if ((size_t)out_size >= OUT_ELEMS + ATTN_ELEMS)
        attn = out + OUT_ELEMS;

    float *Qp, *Kp, *Vp, *Cp;
    cudaGetSymbolAddress((void**)&Qp, g_Q);
    cudaGetSymbolAddress((void**)&Kp, g_K);
    cudaGetSymbolAddress((void**)&Vp, g_V);
    cudaGetSymbolAddress((void**)&Cp, g_ctx);

    cudaFuncSetAttribute(attn_kernel, cudaFuncAttributeMaxDynamicSharedMemorySize,
                         ATT_SMEM_BYTES);

    dim3 pgrid(MODEL_DIM / 128, NROWS / 128);   // (6, 32)
    proj_kernel<<<pgrid, 256>>>(q, wq_w, wq_b, Qp, 1);
    proj_kernel<<<pgrid, 256>>>(k, wk_w, wk_b, Kp, 1);
    proj_kernel<<<pgrid, 256>>>(v, wv_w, wv_b, Vp, 1);

    attn_kernel<<<dim3(BB * NHEAD, SEQ / QT), ATT_THREADS, ATT_SMEM_BYTES>>>(
        Qp, Kp, Vp, attn, Cp);

    proj_kernel<<<pgrid, 256>>>(Cp, wo_w, wo_b, out, 0);
}

// round 3
// speedup vs baseline: 1.0391x; 1.0391x over previous
#include <cuda_runtime.h>

#define MODEL_DIM 768
#define NHEAD 12
#define HD 64
#define BB 2
#define SEQ 2048
#define NROWS (BB * SEQ)                 // 4096
#define OUT_ELEMS ((size_t)NROWS * MODEL_DIM)                 // 3,145,728
#define ATTN_ELEMS ((size_t)BB * NHEAD * SEQ * SEQ)           // 100,663,296

// ---- device scratch (allocation-free) ----
__device__ float g_Q[BB * NHEAD * SEQ * HD];   // [B,H,S,Dh]
__device__ float g_K[BB * NHEAD * SEQ * HD];
__device__ float g_V[BB * NHEAD * SEQ * HD];
__device__ float g_ctx[NROWS * MODEL_DIM];     // [B,S,D]

// ============================================================================
// GEMM: out = X @ W^T + bias.  (unchanged from R1 — not the bottleneck yet)
// ============================================================================
__global__ __launch_bounds__(256)
void proj_kernel(const float* __restrict__ X, const float* __restrict__ W,
                 const float* __restrict__ bias, float* __restrict__ out, int split)
{
    __shared__ float Xs[8][128];
    __shared__ float Ws[8][128];
    const int tid = threadIdx.x;
    const int tx = tid & 15, ty = tid >> 4;
    const int n0 = blockIdx.y * 128;
    const int j0 = blockIdx.x * 128;
    const int lrow = tid >> 1;
    const int ld4  = (tid & 1) * 4;

    float acc[8][8];
#pragma unroll
    for (int i = 0; i < 8; i++)
#pragma unroll
        for (int j = 0; j < 8; j++) acc[i][j] = 0.f;

    const float* Xp = X + (size_t)(n0 + lrow) * MODEL_DIM + ld4;
    const float* Wp = W + (size_t)(j0 + lrow) * MODEL_DIM + ld4;

    for (int d0 = 0; d0 < MODEL_DIM; d0 += 8) {
        float4 xa = *(const float4*)(Xp + d0);
        float4 wa = *(const float4*)(Wp + d0);
        __syncthreads();
        Xs[ld4 + 0][lrow] = xa.x; Xs[ld4 + 1][lrow] = xa.y;
        Xs[ld4 + 2][lrow] = xa.z; Xs[ld4 + 3][lrow] = xa.w;
        Ws[ld4 + 0][lrow] = wa.x; Ws[ld4 + 1][lrow] = wa.y;
        Ws[ld4 + 2][lrow] = wa.z; Ws[ld4 + 3][lrow] = wa.w;
        __syncthreads();
#pragma unroll
        for (int kk = 0; kk < 8; kk++) {
            float a[8], b[8];
            *(float4*)&a[0] = *(const float4*)&Xs[kk][ty * 8];
            *(float4*)&a[4] = *(const float4*)&Xs[kk][ty * 8 + 4];
            *(float4*)&b[0] = *(const float4*)&Ws[kk][tx * 8];
            *(float4*)&b[4] = *(const float4*)&Ws[kk][tx * 8 + 4];
#pragma unroll
            for (int i = 0; i < 8; i++)
#pragma unroll
                for (int j = 0; j < 8; j++) acc[i][j] += a[i] * b[j];
        }
    }

#pragma unroll
    for (int i = 0; i < 8; i++) {
        int n = n0 + ty * 8 + i;
        int b = n >> 11, s = n & (SEQ - 1);
#pragma unroll
        for (int j4 = 0; j4 < 8; j4 += 4) {
            int j = j0 + tx * 8 + j4;
            float4 v;
            v.x = acc[i][j4 + 0] + bias[j + 0];
            v.y = acc[i][j4 + 1] + bias[j + 1];
            v.z = acc[i][j4 + 2] + bias[j + 2];
            v.w = acc[i][j4 + 3] + bias[j + 3];
            if (split) {
                int h = j >> 6, dh = j & 63;
                *(float4*)&out[(((size_t)(b * NHEAD + h) * SEQ + s) << 6) + dh] = v;
            } else {
                *(float4*)&out[(size_t)n * MODEL_DIM + j] = v;
            }
        }
    }
}

// ============================================================================
// Attention, register-tiled.
// Block = (b*h, 16 q rows). Full score rows in smem (exact one-pass softmax).
// smem: sc[16][2048] (128KB) + qs[16][64] (4KB) + buf 64KB (K-tiles / V partials)
//     = 200,704 B dynamic.
// Phase 1: scores GEMM, 4q x 4k microtile over KT=512, d split in halves of 32.
//          2 bytes LDS per FMA -> FMA-floor bound.
// Phase 3: split-K over 16 warps (128 k each), V straight from L2, P via
//          warp-uniform float4 broadcasts, smem cross-warp reduction.
// ============================================================================
#define QT 16
#define ATT_THREADS 512
#define KT1 512
#define SC_FLOATS (QT * SEQ)            // 32768
#define QS_FLOATS (QT * HD)             // 1024
#define BUF_FLOATS (32 * KT1)           // 16384 (also holds 16x1024 partials)
#define ATT_SMEM_BYTES ((SC_FLOATS + QS_FLOATS + BUF_FLOATS) * 4)

__global__ __launch_bounds__(ATT_THREADS, 1)
void attn_kernel(const float* __restrict__ Qg, const float* __restrict__ Kg,
                 const float* __restrict__ Vg, float* __restrict__ attn_out,
                 float* __restrict__ ctx)
{
    extern __shared__ float sm[];
    float* sc  = sm;                         // [QT][SEQ]
    float* qs  = sm + SC_FLOATS;             // [QT][HD]
    float* buf = qs + QS_FLOATS;             // kvt[32][512] OR part[16][1024]

    const int tid = threadIdx.x;
    const int bh = blockIdx.x;               // 0..23
    const int q0 = blockIdx.y * QT;
    const size_t headbase = (size_t)bh * SEQ * HD;
    const float scale = 0.125f;              // 1/sqrt(64)

    // load Q tile (contiguous 16x64)
    for (int l = tid; l < QT * HD; l += ATT_THREADS)
        qs[l] = Qg[headbase + (size_t)q0 * HD + l];

    // ---- Phase 1: scores = Q K^T * scale (4q x 4k microtile) ----
    {
        const int ty = tid >> 7;             // 0..3  -> q rows ty*4..ty*4+3
        const int tx = tid & 127;            // 0..127 -> k cols tx*4..tx*4+3
        for (int kt = 0; kt < SEQ; kt += KT1) {
            float acc[4][4];
#pragma unroll
            for (int i = 0; i < 4; i++)
#pragma unroll
                for (int j = 0; j < 4; j++) acc[i][j] = 0.f;

#pragma unroll
            for (int dh = 0; dh < HD; dh += 32) {
                __syncthreads();             // buf free for refill
                // fill kvt[32][512]: thread owns k = tid
                {
                    const float4* src = (const float4*)(Kg + headbase
                                        + (size_t)(kt + tid) * HD + dh);
#pragma unroll
                    for (int m = 0; m < 8; m++) {
                        float4 kx = __ldg(src + m);
                        buf[(m * 4 + 0) * KT1 + tid] = kx.x;
                        buf[(m * 4 + 1) * KT1 + tid] = kx.y;
                        buf[(m * 4 + 2) * KT1 + tid] = kx.z;
                        buf[(m * 4 + 3) * KT1 + tid] = kx.w;
                    }
                }
                __syncthreads();
#pragma unroll 8
                for (int d = 0; d < 32; d++) {
                    const float* qrow = qs + ty * 256 + dh + d;
                    float a0 = qrow[0], a1 = qrow[64], a2 = qrow[128], a3 = qrow[192];
                    float4 b = *(const float4*)&buf[d * KT1 + tx * 4];
                    acc[0][0] += a0 * b.x; acc[0][1] += a0 * b.y;
                    acc[0][2] += a0 * b.z; acc[0][3] += a0 * b.w;
                    acc[1][0] += a1 * b.x; acc[1][1] += a1 * b.y;
                    acc[1][2] += a1 * b.z; acc[1][3] += a1 * b.w;
                    acc[2][0] += a2 * b.x; acc[2][1] += a2 * b.y;
                    acc[2][2] += a2 * b.z; acc[2][3] += a2 * b.w;
                    acc[3][0] += a3 * b.x; acc[3][1] += a3 * b.y;
                    acc[3][2] += a3 * b.z; acc[3][3] += a3 * b.w;
                }
            }
#pragma unroll
            for (int i = 0; i < 4; i++) {
                float4 s;
                s.x = acc[i][0] * scale; s.y = acc[i][1] * scale;
                s.z = acc[i][2] * scale; s.w = acc[i][3] * scale;
                *(float4*)&sc[(ty * 4 + i) * SEQ + kt + tx * 4] = s;
            }
        }
    }
    __syncthreads();

    // ---- Phase 2: softmax (warp i owns row i) + attn write (streaming) ----
    const int wi = tid >> 5;
    const int lane = tid & 31;
    {
        float* row = sc + wi * SEQ;
        float m = -1e30f;
        for (int c = lane * 4; c < SEQ; c += 128) {
            float4 x = *(const float4*)&row[c];
            m = fmaxf(m, fmaxf(fmaxf(x.x, x.y), fmaxf(x.z, x.w)));
        }
#pragma unroll
        for (int o = 16; o; o >>= 1) m = fmaxf(m, __shfl_xor_sync(0xFFFFFFFFu, m, o));
        float sum = 0.f;
        for (int c = lane * 4; c < SEQ; c += 128) {
            float4 x = *(const float4*)&row[c];
            x.x = __expf(x.x - m); x.y = __expf(x.y - m);
            x.z = __expf(x.z - m); x.w = __expf(x.w - m);
            sum += x.x + x.y + x.z + x.w;
            *(float4*)&row[c] = x;
        }
#pragma unroll
        for (int o = 16; o; o >>= 1) sum += __shfl_xor_sync(0xFFFFFFFFu, sum, o);
        float inv = 1.f / sum;
        float4* arow = attn_out ?
            (float4*)(attn_out + ((size_t)bh * SEQ + q0 + wi) * SEQ) : 0;
        for (int c = lane * 4; c < SEQ; c += 128) {
            float4 x = *(const float4*)&row[c];
            x.x *= inv; x.y *= inv; x.z *= inv; x.w *= inv;
            *(float4*)&row[c] = x;
            if (arow) __stcs(arow + (c >> 2), x);   // streaming: keep K/V in L2
        }
    }
    __syncthreads();                         // all rows final; buf reusable

    // ---- Phase 3: context = P @ V, split-K across warps ----
    {
        const int kbase = wi * 128;          // warp owns 128 k
        const int d0 = lane * 2;             // lane owns d pair
        float c[QT][2];
#pragma unroll
        for (int q = 0; q < QT; q++) { c[q][0] = 0.f; c[q][1] = 0.f; }

        const float* Vh = Vg + headbase;
        for (int kk = 0; kk < 128; kk += 4) {
            int k = kbase + kk;
            float2 v0 = __ldg((const float2*)&Vh[(size_t)(k + 0) * HD + d0]);
            float2 v1 = __ldg((const float2*)&Vh[(size_t)(k + 1) * HD + d0]);
            float2 v2 = __ldg((const float2*)&Vh[(size_t)(k + 2) * HD + d0]);
            float2 v3 = __ldg((const float2*)&Vh[(size_t)(k + 3) * HD + d0]);
#pragma unroll
            for (int q = 0; q < QT; q++) {
                float4 p = *(const float4*)&sc[q * SEQ + k];  // warp-uniform
                c[q][0] += p.x * v0.x + p.y * v1.x + p.z * v2.x + p.w * v3.x;
                c[q][1] += p.x * v0.y + p.y * v1.y + p.z * v2.y + p.w * v3.y;
            }
        }
        // partials -> smem [16 warps][16 q][64 d]
#pragma unroll
        for (int q = 0; q < QT; q++)
            *(float2*)&buf[wi * 1024 + q * HD + d0] = make_float2(c[q][0], c[q][1]);
    }
    __syncthreads();

    // reduce 16 partials; each thread owns one (q, d-pair)
    {
        const int q = tid >> 5;
        const int d = (tid & 31) * 2;
        float2 s = make_float2(0.f, 0.f);
#pragma unroll
        for (int w = 0; w < 16; w++) {
            float2 p = *(const float2*)&buf[w * 1024 + q * HD + d];
            s.x += p.x; s.y += p.y;
        }
        int b = bh / NHEAD, h = bh % NHEAD;
        size_t o = ((size_t)(b * SEQ + q0 + q)) * MODEL_DIM + h * HD + d;
        *(float2*)&ctx[o] = s;
    }
}

// ============================================================================
// launch
// ============================================================================
extern "C" void kernel_launch(void* const* d_in, const int* in_sizes, int n_in,
                              void* d_out, int out_size)
{
    const float* q    = (const float*)d_in[0];
    const float* k    = (const float*)d_in[1];
    const float* v    = (const float*)d_in[2];
    const float* wq_w = (const float*)d_in[3];
    const float* wq_b = (const float*)d_in[4];
    const float* wk_w = (const float*)d_in[5];
    const float* wk_b = (const float*)d_in[6];
    const float* wv_w = (const float*)d_in[7];
    const float* wv_b = (const float*)d_in[8];
    const float* wo_w = (const float*)d_in[9];
    const float* wo_b = (const float*)d_in[10];

    float* out = (float*)d_out;
    float* attn = 0;
    if ((size_t)out_size >= OUT_ELEMS + ATTN_ELEMS)
        attn = out + OUT_ELEMS;

    float *Qp, *Kp, *Vp, *Cp;
    cudaGetSymbolAddress((void**)&Qp, g_Q);
    cudaGetSymbolAddress((void**)&Kp, g_K);
    cudaGetSymbolAddress((void**)&Vp, g_V);
    cudaGetSymbolAddress((void**)&Cp, g_ctx);

    cudaFuncSetAttribute(attn_kernel, cudaFuncAttributeMaxDynamicSharedMemorySize,
                         ATT_SMEM_BYTES);

    dim3 pgrid(MODEL_DIM / 128, NROWS / 128);   // (6, 32)
    proj_kernel<<<pgrid, 256>>>(q, wq_w, wq_b, Qp, 1);
    proj_kernel<<<pgrid, 256>>>(k, wk_w, wk_b, Kp, 1);
    proj_kernel<<<pgrid, 256>>>(v, wv_w, wv_b, Vp, 1);

    attn_kernel<<<dim3(BB * NHEAD, SEQ / QT), ATT_THREADS, ATT_SMEM_BYTES>>>(
        Qp, Kp, Vp, attn, Cp);

    proj_kernel<<<pgrid, 256>>>(Cp, wo_w, wo_b, out, 0);
}